// round 13
// baseline (speedup 1.0000x reference)
#include <cuda_runtime.h>
#include <cuda_fp16.h>
#include <cstdint>
#include <math.h>

// Problem constants (from reference setup_inputs)
#define T_TOK 4096      // B*S
#define D_DIM 1024
#define F_DIM 2048
#define E_NUM 8
#define NGRP  9         // group 0 = shared expert, groups 1..8 = routed experts
#define MAXROWS (3*T_TOK)

// ---------------- device scratch ----------------
__device__ int    g_cnt[E_NUM];
__device__ int    g_fill[E_NUM];
__device__ int    g_start[NGRP];
__device__ int    g_gcnt[NGRP];
__device__ int    g_topi[T_TOK * 2];
__device__ float  g_topw[T_TOK * 2];
__device__ int    g_tok[MAXROWS];
__device__ float  g_wt[MAXROWS];
__device__ int    g_rowof[T_TOK * 2];
__device__ float  g_Y[(size_t)MAXROWS * D_DIM];
// fp16 operands
__device__ __half g_xh [(size_t)T_TOK * D_DIM];            // x, [t][d] k-major
__device__ __half g_Hh [(size_t)MAXROWS * F_DIM];          // gelu(up), [row][f]
__device__ __half g_Wuh[(size_t)E_NUM * F_DIM * D_DIM];    // Wu^T  [e][f][d]
__device__ __half g_Wdh[(size_t)E_NUM * D_DIM * F_DIM];    // Wd^T  [e][d][f]
__device__ __half g_W1h[(size_t)F_DIM * D_DIM];            // W1^T  [f][d]
__device__ __half g_W2h[(size_t)D_DIM * F_DIM];            // W2^T  [d][f]

// ---------------- helpers ----------------
__device__ __forceinline__ void mma_f16(float c[4], const uint32_t a[4],
                                        const uint32_t b[2]) {
    asm("mma.sync.aligned.m16n8k16.row.col.f32.f16.f16.f32 "
        "{%0,%1,%2,%3},{%4,%5,%6,%7},{%8,%9},{%0,%1,%2,%3};"
        : "+f"(c[0]), "+f"(c[1]), "+f"(c[2]), "+f"(c[3])
        : "r"(a[0]), "r"(a[1]), "r"(a[2]), "r"(a[3]), "r"(b[0]), "r"(b[1]));
}
__device__ __forceinline__ void ldsm_x4(uint32_t& r0, uint32_t& r1,
                                        uint32_t& r2, uint32_t& r3, uint32_t addr) {
    asm volatile("ldmatrix.sync.aligned.m8n8.x4.shared.b16 {%0,%1,%2,%3}, [%4];"
                 : "=r"(r0), "=r"(r1), "=r"(r2), "=r"(r3) : "r"(addr));
}
__device__ __forceinline__ void cp16(void* smem_dst, const void* gsrc) {
    uint32_t d = (uint32_t)__cvta_generic_to_shared(smem_dst);
    asm volatile("cp.async.ca.shared.global [%0], [%1], 16;\n" ::"r"(d), "l"(gsrc));
}
#define CP_COMMIT() asm volatile("cp.async.commit_group;")
#define CP_WAIT(n)  asm volatile("cp.async.wait_group %0;" ::"n"(n))

// ---------------- small kernels ----------------
__global__ void init_kernel() {
    int i = threadIdx.x;
    if (i < E_NUM) { g_cnt[i] = 0; g_fill[i] = 0; }
}

__global__ void convert_x_kernel(const float* __restrict__ src) {
    int i = blockIdx.x * blockDim.x + threadIdx.x;
    if (i >= T_TOK * (D_DIM / 4)) return;
    float4 v = ((const float4*)src)[i];
    ((__half2*)g_xh)[i * 2 + 0] = __floats2half2_rn(v.x, v.y);
    ((__half2*)g_xh)[i * 2 + 1] = __floats2half2_rn(v.z, v.w);
}

// tiled transpose + fp32->fp16: in [K][N] float -> out [N][K] half (batched)
__global__ void transpose_h_kernel(const float* __restrict__ in,
                                   __half* __restrict__ out, int K, int N) {
    __shared__ float t[32][33];
    const size_t boff = (size_t)blockIdx.z * K * N;
    in  += boff;
    out += boff;
    int k0 = blockIdx.y * 32, n0 = blockIdx.x * 32;
    int tx = threadIdx.x, ty = threadIdx.y;  // 32 x 8
#pragma unroll
    for (int j = 0; j < 32; j += 8)
        t[ty + j][tx] = in[(size_t)(k0 + ty + j) * N + n0 + tx];
    __syncthreads();
#pragma unroll
    for (int j = 0; j < 32; j += 8)
        out[(size_t)(n0 + ty + j) * K + k0 + tx] = __float2half_rn(t[tx][ty + j]);
}

__global__ void router_kernel(const float* __restrict__ x,
                              const float* __restrict__ Wg) {
    int warp = (blockIdx.x * blockDim.x + threadIdx.x) >> 5;
    int lane = threadIdx.x & 31;
    if (warp >= T_TOK) return;
    const float* xr = x + (size_t)warp * D_DIM;
    float acc[E_NUM];
#pragma unroll
    for (int e = 0; e < E_NUM; e++) acc[e] = 0.f;
    for (int i = 0; i < D_DIM / 32; i++) {
        int d = i * 32 + lane;
        float xv = xr[d];
        const float4* wr = (const float4*)(Wg + (size_t)d * E_NUM);
        float4 w0 = wr[0], w1 = wr[1];
        acc[0] += xv * w0.x; acc[1] += xv * w0.y;
        acc[2] += xv * w0.z; acc[3] += xv * w0.w;
        acc[4] += xv * w1.x; acc[5] += xv * w1.y;
        acc[6] += xv * w1.z; acc[7] += xv * w1.w;
    }
#pragma unroll
    for (int e = 0; e < E_NUM; e++)
#pragma unroll
        for (int o = 16; o > 0; o >>= 1)
            acc[e] += __shfl_down_sync(0xffffffffu, acc[e], o);
    if (lane == 0) {
        int b0 = -1, b1 = -1;
        float v0 = -1e30f, v1 = -1e30f;
#pragma unroll
        for (int e = 0; e < E_NUM; e++) {
            float v = acc[e];
            if (v > v0) { v1 = v0; b1 = b0; v0 = v; b0 = e; }
            else if (v > v1) { v1 = v; b1 = e; }
        }
        float w0 = 1.f / (1.f + expf(v1 - v0));
        g_topi[warp * 2 + 0] = b0; g_topw[warp * 2 + 0] = w0;
        g_topi[warp * 2 + 1] = b1; g_topw[warp * 2 + 1] = 1.f - w0;
        atomicAdd(&g_cnt[b0], 1);
        atomicAdd(&g_cnt[b1], 1);
    }
}

// fill + fused scan
__global__ void fill_kernel() {
    int t = blockIdx.x * blockDim.x + threadIdx.x;
    if (t >= T_TOK) return;
    int st[E_NUM];
    {
        int off = T_TOK;
#pragma unroll
        for (int e = 0; e < E_NUM; e++) { st[e] = off; off += g_cnt[e]; }
    }
    if (t == 0) {
        g_start[0] = 0; g_gcnt[0] = T_TOK;
#pragma unroll
        for (int e = 0; e < E_NUM; e++) {
            g_start[e + 1] = st[e];
            g_gcnt[e + 1]  = g_cnt[e];
        }
    }
    g_tok[t] = t; g_wt[t] = 1.f;
#pragma unroll
    for (int j = 0; j < 2; j++) {
        int e = g_topi[t * 2 + j];
        int r = st[e] + atomicAdd(&g_fill[e], 1);
        g_tok[r] = t;
        g_wt[r]  = g_topw[t * 2 + j];
        g_rowof[t * 2 + j] = r;
    }
}

__device__ __forceinline__ float gelu_erf(float v) {
    return 0.5f * v * (1.f + erff(v * 0.70710678118654752440f));
}

// ---------------- grouped FP16 tensor-core GEMM ----------------
// 128x128 block tile, 256 threads (8 warps 2m x 4n, warp tile 64x32), BK=64,
// mma m16n8k16 fed by ldmatrix.x4, 3-stage cp.async pipeline, 2 CTAs/SM.
// BK=64 halves barrier/wait count vs BK=32 and doubles ILP between syncs.
// Stride 72 halves (144B): ldmatrix 8-row phases hit quad-banks {0,4,..,28}
// each 16B wide -> all 32 banks exactly once, conflict-free.
#define STAGES 3
#define BKH 64                              // K halves per stage
#define AS 72                               // halves per smem row (64 + 8 pad)
#define A_STG_H (128 * AS)                  // 9216 halves
#define B_STG_H (128 * AS)                  // 9216 halves
#define STG_H   (A_STG_H + B_STG_H)         // 18432 halves = 36864 B
#define SMEM_SZ (STAGES * STG_H * 2)        // 110592 B

template<int KDIM, int NDIM, bool UP>
__global__ __launch_bounds__(256, 2)
void grouped_gemm_f16(const __half* __restrict__ Bexp,
                      const __half* __restrict__ Bsh) {
    extern __shared__ __half smem[];

    const int g   = blockIdx.z;
    const int cnt = g_gcnt[g];
    const int m0  = blockIdx.x * 128;
    if (m0 >= cnt) return;
    const int start = g_start[g];
    const int n0    = blockIdx.y * 128;

    const __half* __restrict__ Bmat =
        (g == 0) ? Bsh : (Bexp + (size_t)(g - 1) * KDIM * NDIM);
    const __half* __restrict__ Asrc = UP ? g_xh : g_Hh;

    const int tid  = threadIdx.x;
    const int warp = tid >> 5;
    const int lane = tid & 31;
    const int gid  = lane >> 2;   // 0..7
    const int tig  = lane & 3;    // 0..3
    const int wm   = (warp >> 2) * 64;   // 0,64
    const int wn   = (warp & 3) * 32;    // 0,32,64,96

    // ldmatrix.x4 per-lane offsets (halves, added to tile base):
    const int a_off = (((lane >> 3) & 1) * 8 + (lane & 7)) * AS + (lane >> 4) * 8;
    const int b_off = ((lane >> 4) * 8 + (lane & 7)) * AS + ((lane >> 3) & 1) * 8;

    // --- load geometry (per BK=64 stage): row = tid>>1, 4 chunks of 16B ---
    const int lrow = tid >> 1;          // 0..127
    const int lc0  = (tid & 1) * 8;     // first chunk offset (halves)
    int gr = m0 + lrow; if (gr >= cnt) gr = cnt - 1;
    const int sr = UP ? g_tok[start + gr] : (start + gr);
    const __half* pA = Asrc + (size_t)sr * KDIM + lc0;
    const __half* pB = Bmat + (size_t)(n0 + lrow) * KDIM + lc0;

    float c[4][4][4];
#pragma unroll
    for (int i = 0; i < 4; i++)
#pragma unroll
        for (int j = 0; j < 4; j++)
#pragma unroll
            for (int k = 0; k < 4; k++) c[i][j][k] = 0.f;

    const int KT = KDIM / BKH;

    __half* As[STAGES];
    __half* Bs[STAGES];
#pragma unroll
    for (int s = 0; s < STAGES; s++) {
        As[s] = smem + s * STG_H;
        Bs[s] = As[s] + A_STG_H;
    }
    const uint32_t sbase = (uint32_t)__cvta_generic_to_shared(smem);

    // prologue: stages 0..1
#pragma unroll
    for (int s = 0; s < STAGES - 1; s++) {
        const int kb = s * BKH;
#pragma unroll
        for (int j = 0; j < 4; j++) {
            cp16(&As[s][lrow * AS + lc0 + 16 * j], pA + kb + 16 * j);
            cp16(&Bs[s][lrow * AS + lc0 + 16 * j], pB + kb + 16 * j);
        }
        CP_COMMIT();
    }

    for (int kt = 0; kt < KT; kt++) {
        CP_WAIT(STAGES - 2);   // stage kt landed
        __syncthreads();       // everyone done with the buffer being refilled

        const int kn = kt + STAGES - 1;
        if (kn < KT) {
            __half* An = As[kn % STAGES];
            __half* Bn = Bs[kn % STAGES];
            const int kb = kn * BKH;
#pragma unroll
            for (int j = 0; j < 4; j++) {
                cp16(&An[lrow * AS + lc0 + 16 * j], pA + kb + 16 * j);
                cp16(&Bn[lrow * AS + lc0 + 16 * j], pB + kb + 16 * j);
            }
        }
        CP_COMMIT();

        const uint32_t aU = sbase + (uint32_t)((kt % STAGES) * STG_H) * 2;
        const uint32_t bU = aU + A_STG_H * 2;
#pragma unroll
        for (int ks = 0; ks < BKH / 16; ks++) {
            const int kb = ks * 16;
            uint32_t af[4][4], bf[4][2];
#pragma unroll
            for (int mt = 0; mt < 4; mt++) {
                uint32_t ad = aU + 2u * ((wm + mt * 16) * AS + kb + a_off);
                ldsm_x4(af[mt][0], af[mt][1], af[mt][2], af[mt][3], ad);
            }
#pragma unroll
            for (int p = 0; p < 2; p++) {
                uint32_t bd = bU + 2u * ((wn + p * 16) * AS + kb + b_off);
                ldsm_x4(bf[2 * p][0], bf[2 * p][1], bf[2 * p + 1][0], bf[2 * p + 1][1], bd);
            }
#pragma unroll
            for (int mt = 0; mt < 4; mt++)
#pragma unroll
                for (int nt = 0; nt < 4; nt++)
                    mma_f16(c[mt][nt], af[mt], bf[nt]);
        }
    }

    // ---------------- epilogue ----------------
#pragma unroll
    for (int mt = 0; mt < 4; mt++) {
        int r0 = m0 + wm + mt * 16 + gid;
        int r1 = r0 + 8;
        float w0 = 1.f, w1 = 1.f;
        if (!UP) {
            if (r0 < cnt) w0 = g_wt[start + r0];
            if (r1 < cnt) w1 = g_wt[start + r1];
        }
#pragma unroll
        for (int nt = 0; nt < 4; nt++) {
            int col = n0 + wn + nt * 8 + tig * 2;
            if (UP) {
                if (r0 < cnt) {
                    __half2 h = __floats2half2_rn(gelu_erf(c[mt][nt][0]),
                                                  gelu_erf(c[mt][nt][1]));
                    *(__half2*)&g_Hh[(size_t)(start + r0) * NDIM + col] = h;
                }
                if (r1 < cnt) {
                    __half2 h = __floats2half2_rn(gelu_erf(c[mt][nt][2]),
                                                  gelu_erf(c[mt][nt][3]));
                    *(__half2*)&g_Hh[(size_t)(start + r1) * NDIM + col] = h;
                }
            } else {
                if (r0 < cnt) {
                    float2 v = make_float2(c[mt][nt][0] * w0, c[mt][nt][1] * w0);
                    *(float2*)&g_Y[(size_t)(start + r0) * NDIM + col] = v;
                }
                if (r1 < cnt) {
                    float2 v = make_float2(c[mt][nt][2] * w1, c[mt][nt][3] * w1);
                    *(float2*)&g_Y[(size_t)(start + r1) * NDIM + col] = v;
                }
            }
        }
    }
}

// ---------------- combine ----------------
__global__ void combine_kernel(float* __restrict__ out) {
    int i = blockIdx.x * blockDim.x + threadIdx.x;
    if (i >= T_TOK * (D_DIM / 4)) return;
    int t  = i / (D_DIM / 4);
    int c4 = i - t * (D_DIM / 4);
    int r0 = g_rowof[t * 2 + 0];
    int r1 = g_rowof[t * 2 + 1];
    float4 s = ((const float4*)(g_Y + (size_t)t  * D_DIM))[c4];
    float4 a = ((const float4*)(g_Y + (size_t)r0 * D_DIM))[c4];
    float4 b = ((const float4*)(g_Y + (size_t)r1 * D_DIM))[c4];
    float4 o;
    o.x = s.x + a.x + b.x;
    o.y = s.y + a.y + b.y;
    o.z = s.z + a.z + b.z;
    o.w = s.w + a.w + b.w;
    ((float4*)out)[i] = o;
}

// ---------------- launcher ----------------
static __half* dev_hptr(const void* sym) {
    void* p = nullptr;
    cudaGetSymbolAddress(&p, (const void*)sym);
    return (__half*)p;
}

extern "C" void kernel_launch(void* const* d_in, const int* in_sizes, int n_in,
                              void* d_out, int out_size) {
    const float* x  = (const float*)d_in[0];
    const float* Wg = (const float*)d_in[1];
    const float* Wu = (const float*)d_in[2];
    const float* Wd = (const float*)d_in[3];
    const float* W1 = (const float*)d_in[4];
    const float* W2 = (const float*)d_in[5];
    float* out = (float*)d_out;

    cudaFuncSetAttribute(grouped_gemm_f16<D_DIM, F_DIM, true>,
                         cudaFuncAttributeMaxDynamicSharedMemorySize, SMEM_SZ);
    cudaFuncSetAttribute(grouped_gemm_f16<F_DIM, D_DIM, false>,
                         cudaFuncAttributeMaxDynamicSharedMemorySize, SMEM_SZ);

    __half* Wuh = dev_hptr(g_Wuh);
    __half* Wdh = dev_hptr(g_Wdh);
    __half* W1h = dev_hptr(g_W1h);
    __half* W2h = dev_hptr(g_W2h);

    init_kernel<<<1, 32>>>();
    router_kernel<<<T_TOK / 8, 256>>>(x, Wg);
    fill_kernel<<<(T_TOK + 255) / 256, 256>>>();

    // fp16 operand prep (all pre-GEMM)
    convert_x_kernel<<<(T_TOK * (D_DIM / 4) + 255) / 256, 256>>>(x);
    {
        dim3 thr(32, 8);
        transpose_h_kernel<<<dim3(F_DIM / 32, D_DIM / 32, E_NUM), thr>>>(Wu, Wuh, D_DIM, F_DIM);
        transpose_h_kernel<<<dim3(D_DIM / 32, F_DIM / 32, E_NUM), thr>>>(Wd, Wdh, F_DIM, D_DIM);
        transpose_h_kernel<<<dim3(F_DIM / 32, D_DIM / 32, 1), thr>>>(W1, W1h, D_DIM, F_DIM);
        transpose_h_kernel<<<dim3(D_DIM / 32, F_DIM / 32, 1), thr>>>(W2, W2h, F_DIM, D_DIM);
    }

    // up-proj + GELU: N = F = 2048 (16 tiles), K = D = 1024
    grouped_gemm_f16<D_DIM, F_DIM, true>
        <<<dim3(T_TOK / 128, F_DIM / 128, NGRP), 256, SMEM_SZ>>>(Wuh, W1h);

    // down-proj + combine weight: N = D = 1024 (8 tiles), K = F = 2048
    grouped_gemm_f16<F_DIM, D_DIM, false>
        <<<dim3(T_TOK / 128, D_DIM / 128, NGRP), 256, SMEM_SZ>>>(Wdh, W2h);

    combine_kernel<<<(T_TOK * (D_DIM / 4) + 255) / 256, 256>>>(out);
}

// round 16
// speedup vs baseline: 1.2157x; 1.2157x over previous
#include <cuda_runtime.h>
#include <cuda_fp16.h>
#include <cstdint>
#include <math.h>

// Problem constants (from reference setup_inputs)
#define T_TOK 4096      // B*S
#define D_DIM 1024
#define F_DIM 2048
#define E_NUM 8
#define NGRP  9         // group 0 = shared expert, groups 1..8 = routed experts
#define MAXROWS (3*T_TOK)

// ---------------- device scratch ----------------
__device__ int    g_cnt[E_NUM];
__device__ int    g_fill[E_NUM];
__device__ int    g_start[NGRP];
__device__ int    g_gcnt[NGRP];
__device__ int    g_topi[T_TOK * 2];
__device__ float  g_topw[T_TOK * 2];
__device__ int    g_tok[MAXROWS];
__device__ float  g_wt[MAXROWS];
__device__ int    g_rowof[T_TOK * 2];
__device__ float  g_Y[(size_t)MAXROWS * D_DIM];
// fp16 operands
__device__ __half g_xh [(size_t)T_TOK * D_DIM];            // x, [t][d] k-major
__device__ __half g_Hh [(size_t)MAXROWS * F_DIM];          // gelu(up), [row][f]
__device__ __half g_Wuh[(size_t)E_NUM * F_DIM * D_DIM];    // Wu^T  [e][f][d]
__device__ __half g_Wdh[(size_t)E_NUM * D_DIM * F_DIM];    // Wd^T  [e][d][f]
__device__ __half g_W1h[(size_t)F_DIM * D_DIM];            // W1^T  [f][d]
__device__ __half g_W2h[(size_t)D_DIM * F_DIM];            // W2^T  [d][f]

// ---------------- helpers ----------------
__device__ __forceinline__ void mma_f16(float c[4], const uint32_t a[4],
                                        const uint32_t b[2]) {
    asm("mma.sync.aligned.m16n8k16.row.col.f32.f16.f16.f32 "
        "{%0,%1,%2,%3},{%4,%5,%6,%7},{%8,%9},{%0,%1,%2,%3};"
        : "+f"(c[0]), "+f"(c[1]), "+f"(c[2]), "+f"(c[3])
        : "r"(a[0]), "r"(a[1]), "r"(a[2]), "r"(a[3]), "r"(b[0]), "r"(b[1]));
}
__device__ __forceinline__ void ldsm_x4(uint32_t& r0, uint32_t& r1,
                                        uint32_t& r2, uint32_t& r3, uint32_t addr) {
    asm volatile("ldmatrix.sync.aligned.m8n8.x4.shared.b16 {%0,%1,%2,%3}, [%4];"
                 : "=r"(r0), "=r"(r1), "=r"(r2), "=r"(r3) : "r"(addr));
}
__device__ __forceinline__ void cp16(void* smem_dst, const void* gsrc) {
    uint32_t d = (uint32_t)__cvta_generic_to_shared(smem_dst);
    asm volatile("cp.async.ca.shared.global [%0], [%1], 16;\n" ::"r"(d), "l"(gsrc));
}
#define CP_COMMIT() asm volatile("cp.async.commit_group;")
#define CP_WAIT(n)  asm volatile("cp.async.wait_group %0;" ::"n"(n))

// ---------------- small kernels ----------------
__global__ void init_kernel() {
    int i = threadIdx.x;
    if (i < E_NUM) { g_cnt[i] = 0; g_fill[i] = 0; }
}

__global__ void convert_x_kernel(const float* __restrict__ src) {
    int i = blockIdx.x * blockDim.x + threadIdx.x;
    if (i >= T_TOK * (D_DIM / 4)) return;
    float4 v = ((const float4*)src)[i];
    ((__half2*)g_xh)[i * 2 + 0] = __floats2half2_rn(v.x, v.y);
    ((__half2*)g_xh)[i * 2 + 1] = __floats2half2_rn(v.z, v.w);
}

// tiled transpose + fp32->fp16: in [K][N] float -> out [N][K] half (batched)
__global__ void transpose_h_kernel(const float* __restrict__ in,
                                   __half* __restrict__ out, int K, int N) {
    __shared__ float t[32][33];
    const size_t boff = (size_t)blockIdx.z * K * N;
    in  += boff;
    out += boff;
    int k0 = blockIdx.y * 32, n0 = blockIdx.x * 32;
    int tx = threadIdx.x, ty = threadIdx.y;  // 32 x 8
#pragma unroll
    for (int j = 0; j < 32; j += 8)
        t[ty + j][tx] = in[(size_t)(k0 + ty + j) * N + n0 + tx];
    __syncthreads();
#pragma unroll
    for (int j = 0; j < 32; j += 8)
        out[(size_t)(n0 + ty + j) * K + k0 + tx] = __float2half_rn(t[tx][ty + j]);
}

__global__ void router_kernel(const float* __restrict__ x,
                              const float* __restrict__ Wg) {
    int warp = (blockIdx.x * blockDim.x + threadIdx.x) >> 5;
    int lane = threadIdx.x & 31;
    if (warp >= T_TOK) return;
    const float* xr = x + (size_t)warp * D_DIM;
    float acc[E_NUM];
#pragma unroll
    for (int e = 0; e < E_NUM; e++) acc[e] = 0.f;
    for (int i = 0; i < D_DIM / 32; i++) {
        int d = i * 32 + lane;
        float xv = xr[d];
        const float4* wr = (const float4*)(Wg + (size_t)d * E_NUM);
        float4 w0 = wr[0], w1 = wr[1];
        acc[0] += xv * w0.x; acc[1] += xv * w0.y;
        acc[2] += xv * w0.z; acc[3] += xv * w0.w;
        acc[4] += xv * w1.x; acc[5] += xv * w1.y;
        acc[6] += xv * w1.z; acc[7] += xv * w1.w;
    }
#pragma unroll
    for (int e = 0; e < E_NUM; e++)
#pragma unroll
        for (int o = 16; o > 0; o >>= 1)
            acc[e] += __shfl_down_sync(0xffffffffu, acc[e], o);
    if (lane == 0) {
        int b0 = -1, b1 = -1;
        float v0 = -1e30f, v1 = -1e30f;
#pragma unroll
        for (int e = 0; e < E_NUM; e++) {
            float v = acc[e];
            if (v > v0) { v1 = v0; b1 = b0; v0 = v; b0 = e; }
            else if (v > v1) { v1 = v; b1 = e; }
        }
        float w0 = 1.f / (1.f + expf(v1 - v0));
        g_topi[warp * 2 + 0] = b0; g_topw[warp * 2 + 0] = w0;
        g_topi[warp * 2 + 1] = b1; g_topw[warp * 2 + 1] = 1.f - w0;
        atomicAdd(&g_cnt[b0], 1);
        atomicAdd(&g_cnt[b1], 1);
    }
}

// fill + fused scan
__global__ void fill_kernel() {
    int t = blockIdx.x * blockDim.x + threadIdx.x;
    if (t >= T_TOK) return;
    int st[E_NUM];
    {
        int off = T_TOK;
#pragma unroll
        for (int e = 0; e < E_NUM; e++) { st[e] = off; off += g_cnt[e]; }
    }
    if (t == 0) {
        g_start[0] = 0; g_gcnt[0] = T_TOK;
#pragma unroll
        for (int e = 0; e < E_NUM; e++) {
            g_start[e + 1] = st[e];
            g_gcnt[e + 1]  = g_cnt[e];
        }
    }
    g_tok[t] = t; g_wt[t] = 1.f;
#pragma unroll
    for (int j = 0; j < 2; j++) {
        int e = g_topi[t * 2 + j];
        int r = st[e] + atomicAdd(&g_fill[e], 1);
        g_tok[r] = t;
        g_wt[r]  = g_topw[t * 2 + j];
        g_rowof[t * 2 + j] = r;
    }
}

__device__ __forceinline__ float gelu_erf(float v) {
    return 0.5f * v * (1.f + erff(v * 0.70710678118654752440f));
}

// ---------------- grouped FP16 tensor-core GEMM ----------------
// 128x128 block tile, 256 threads (8 warps 2m x 4n, warp tile 64x32), BK=32,
// mma m16n8k16 fed by ldmatrix.x4, 4-stage cp.async pipeline, 2 CTAs/SM.
// (R13 lesson: BK=64's smem dropped to 1 CTA/SM -> regression. Deepen the
// pipeline, not the chunk: 4 stages = 81,920B/CTA, still 2 CTAs/SM.)
// Stride 40 halves (80B): ldmatrix 8-row phases hit all 32 banks -> conflict-free.
#define STAGES 4
#define AS 40                               // halves per smem row (32 + 8 pad)
#define A_STG_H (128 * AS)                  // 5120 halves
#define B_STG_H (128 * AS)                  // 5120 halves
#define STG_H   (A_STG_H + B_STG_H)         // 10240 halves = 20480 B
#define SMEM_SZ (STAGES * STG_H * 2)        // 81920 B

template<int KDIM, int NDIM, bool UP>
__global__ __launch_bounds__(256, 2)
void grouped_gemm_f16(const __half* __restrict__ Bexp,
                      const __half* __restrict__ Bsh) {
    extern __shared__ __half smem[];

    const int g   = blockIdx.z;
    const int cnt = g_gcnt[g];
    const int m0  = blockIdx.x * 128;
    if (m0 >= cnt) return;
    const int start = g_start[g];
    const int n0    = blockIdx.y * 128;

    const __half* __restrict__ Bmat =
        (g == 0) ? Bsh : (Bexp + (size_t)(g - 1) * KDIM * NDIM);
    const __half* __restrict__ Asrc = UP ? g_xh : g_Hh;

    const int tid  = threadIdx.x;
    const int warp = tid >> 5;
    const int lane = tid & 31;
    const int gid  = lane >> 2;   // 0..7
    const int tig  = lane & 3;    // 0..3
    const int wm   = (warp >> 2) * 64;   // 0,64
    const int wn   = (warp & 3) * 32;    // 0,32,64,96

    // ldmatrix.x4 per-lane offsets (halves, added to tile base):
    // A tile m16k16 -> {r0-7 k0-7, r8-15 k0-7, r0-7 k8-15, r8-15 k8-15}
    const int a_off = (((lane >> 3) & 1) * 8 + (lane & 7)) * AS + (lane >> 4) * 8;
    // B pair (two n8k16) -> {n0-7 k0-7, n0-7 k8-15, n8-15 k0-7, n8-15 k8-15}
    const int b_off = ((lane >> 4) * 8 + (lane & 7)) * AS + ((lane >> 3) & 1) * 8;

    // --- load geometry (per BK=32 stage, 256 threads) ---
    const int lrow = tid >> 1;          // 0..127
    const int lch  = (tid & 1) * 8;     // halves offset of first chunk
    int gr = m0 + lrow; if (gr >= cnt) gr = cnt - 1;
    const int sr = UP ? g_tok[start + gr] : (start + gr);
    const __half* pA = Asrc + (size_t)sr * KDIM + lch;
    const __half* pB = Bmat + (size_t)(n0 + lrow) * KDIM + lch;

    float c[4][4][4];
#pragma unroll
    for (int i = 0; i < 4; i++)
#pragma unroll
        for (int j = 0; j < 4; j++)
#pragma unroll
            for (int k = 0; k < 4; k++) c[i][j][k] = 0.f;

    const int KT = KDIM / 32;

    __half* As[STAGES];
    __half* Bs[STAGES];
#pragma unroll
    for (int s = 0; s < STAGES; s++) {
        As[s] = smem + s * STG_H;
        Bs[s] = As[s] + A_STG_H;
    }
    const uint32_t sbase = (uint32_t)__cvta_generic_to_shared(smem);

    // prologue: stages 0..2
#pragma unroll
    for (int s = 0; s < STAGES - 1; s++) {
        const int kb = s * 32;
        cp16(&As[s][lrow * AS + lch],      pA + kb);
        cp16(&As[s][lrow * AS + lch + 16], pA + kb + 16);
        cp16(&Bs[s][lrow * AS + lch],      pB + kb);
        cp16(&Bs[s][lrow * AS + lch + 16], pB + kb + 16);
        CP_COMMIT();
    }

    for (int kt = 0; kt < KT; kt++) {
        CP_WAIT(STAGES - 2);   // stage kt landed (only blocks on 3-iter-old group)
        __syncthreads();       // everyone done with the buffer being refilled

        const int kn = kt + STAGES - 1;
        if (kn < KT) {
            __half* An = As[kn % STAGES];
            __half* Bn = Bs[kn % STAGES];
            const int kb = kn * 32;
            cp16(&An[lrow * AS + lch],      pA + kb);
            cp16(&An[lrow * AS + lch + 16], pA + kb + 16);
            cp16(&Bn[lrow * AS + lch],      pB + kb);
            cp16(&Bn[lrow * AS + lch + 16], pB + kb + 16);
        }
        CP_COMMIT();

        const uint32_t aU = sbase + (uint32_t)((kt % STAGES) * STG_H) * 2;
        const uint32_t bU = aU + A_STG_H * 2;
#pragma unroll
        for (int ks = 0; ks < 2; ks++) {
            const int kb = ks * 16;
            uint32_t af[4][4], bf[4][2];
#pragma unroll
            for (int mt = 0; mt < 4; mt++) {
                uint32_t ad = aU + 2u * ((wm + mt * 16) * AS + kb + a_off);
                ldsm_x4(af[mt][0], af[mt][1], af[mt][2], af[mt][3], ad);
            }
#pragma unroll
            for (int p = 0; p < 2; p++) {
                uint32_t bd = bU + 2u * ((wn + p * 16) * AS + kb + b_off);
                ldsm_x4(bf[2 * p][0], bf[2 * p][1], bf[2 * p + 1][0], bf[2 * p + 1][1], bd);
            }
#pragma unroll
            for (int mt = 0; mt < 4; mt++)
#pragma unroll
                for (int nt = 0; nt < 4; nt++)
                    mma_f16(c[mt][nt], af[mt], bf[nt]);
        }
    }

    // ---------------- epilogue ----------------
#pragma unroll
    for (int mt = 0; mt < 4; mt++) {
        int r0 = m0 + wm + mt * 16 + gid;
        int r1 = r0 + 8;
        float w0 = 1.f, w1 = 1.f;
        if (!UP) {
            if (r0 < cnt) w0 = g_wt[start + r0];
            if (r1 < cnt) w1 = g_wt[start + r1];
        }
#pragma unroll
        for (int nt = 0; nt < 4; nt++) {
            int col = n0 + wn + nt * 8 + tig * 2;
            if (UP) {
                if (r0 < cnt) {
                    __half2 h = __floats2half2_rn(gelu_erf(c[mt][nt][0]),
                                                  gelu_erf(c[mt][nt][1]));
                    *(__half2*)&g_Hh[(size_t)(start + r0) * NDIM + col] = h;
                }
                if (r1 < cnt) {
                    __half2 h = __floats2half2_rn(gelu_erf(c[mt][nt][2]),
                                                  gelu_erf(c[mt][nt][3]));
                    *(__half2*)&g_Hh[(size_t)(start + r1) * NDIM + col] = h;
                }
            } else {
                if (r0 < cnt) {
                    float2 v = make_float2(c[mt][nt][0] * w0, c[mt][nt][1] * w0);
                    *(float2*)&g_Y[(size_t)(start + r0) * NDIM + col] = v;
                }
                if (r1 < cnt) {
                    float2 v = make_float2(c[mt][nt][2] * w1, c[mt][nt][3] * w1);
                    *(float2*)&g_Y[(size_t)(start + r1) * NDIM + col] = v;
                }
            }
        }
    }
}

// ---------------- combine ----------------
__global__ void combine_kernel(float* __restrict__ out) {
    int i = blockIdx.x * blockDim.x + threadIdx.x;
    if (i >= T_TOK * (D_DIM / 4)) return;
    int t  = i / (D_DIM / 4);
    int c4 = i - t * (D_DIM / 4);
    int r0 = g_rowof[t * 2 + 0];
    int r1 = g_rowof[t * 2 + 1];
    float4 s = ((const float4*)(g_Y + (size_t)t  * D_DIM))[c4];
    float4 a = ((const float4*)(g_Y + (size_t)r0 * D_DIM))[c4];
    float4 b = ((const float4*)(g_Y + (size_t)r1 * D_DIM))[c4];
    float4 o;
    o.x = s.x + a.x + b.x;
    o.y = s.y + a.y + b.y;
    o.z = s.z + a.z + b.z;
    o.w = s.w + a.w + b.w;
    ((float4*)out)[i] = o;
}

// ---------------- launcher ----------------
static __half* dev_hptr(const void* sym) {
    void* p = nullptr;
    cudaGetSymbolAddress(&p, (const void*)sym);
    return (__half*)p;
}

extern "C" void kernel_launch(void* const* d_in, const int* in_sizes, int n_in,
                              void* d_out, int out_size) {
    const float* x  = (const float*)d_in[0];
    const float* Wg = (const float*)d_in[1];
    const float* Wu = (const float*)d_in[2];
    const float* Wd = (const float*)d_in[3];
    const float* W1 = (const float*)d_in[4];
    const float* W2 = (const float*)d_in[5];
    float* out = (float*)d_out;

    cudaFuncSetAttribute(grouped_gemm_f16<D_DIM, F_DIM, true>,
                         cudaFuncAttributeMaxDynamicSharedMemorySize, SMEM_SZ);
    cudaFuncSetAttribute(grouped_gemm_f16<F_DIM, D_DIM, false>,
                         cudaFuncAttributeMaxDynamicSharedMemorySize, SMEM_SZ);

    __half* Wuh = dev_hptr(g_Wuh);
    __half* Wdh = dev_hptr(g_Wdh);
    __half* W1h = dev_hptr(g_W1h);
    __half* W2h = dev_hptr(g_W2h);

    init_kernel<<<1, 32>>>();
    router_kernel<<<T_TOK / 8, 256>>>(x, Wg);
    fill_kernel<<<(T_TOK + 255) / 256, 256>>>();

    // fp16 operand prep (all pre-GEMM)
    convert_x_kernel<<<(T_TOK * (D_DIM / 4) + 255) / 256, 256>>>(x);
    {
        dim3 thr(32, 8);
        transpose_h_kernel<<<dim3(F_DIM / 32, D_DIM / 32, E_NUM), thr>>>(Wu, Wuh, D_DIM, F_DIM);
        transpose_h_kernel<<<dim3(D_DIM / 32, F_DIM / 32, E_NUM), thr>>>(Wd, Wdh, F_DIM, D_DIM);
        transpose_h_kernel<<<dim3(F_DIM / 32, D_DIM / 32, 1), thr>>>(W1, W1h, D_DIM, F_DIM);
        transpose_h_kernel<<<dim3(D_DIM / 32, F_DIM / 32, 1), thr>>>(W2, W2h, F_DIM, D_DIM);
    }

    // up-proj + GELU: N = F = 2048 (16 tiles), K = D = 1024
    grouped_gemm_f16<D_DIM, F_DIM, true>
        <<<dim3(T_TOK / 128, F_DIM / 128, NGRP), 256, SMEM_SZ>>>(Wuh, W1h);

    // down-proj + combine weight: N = D = 1024 (8 tiles), K = F = 2048
    grouped_gemm_f16<F_DIM, D_DIM, false>
        <<<dim3(T_TOK / 128, D_DIM / 128, NGRP), 256, SMEM_SZ>>>(Wdh, W2h);

    combine_kernel<<<(T_TOK * (D_DIM / 4) + 255) / 256, 256>>>(out);
}